// round 17
// baseline (speedup 1.0000x reference)
#include <cuda_runtime.h>
#include <math.h>
#include <stdint.h>

// Problem constants
#define Tt   512
#define Bb   64
#define Dd   256
#define Uu   512
#define Mm   64
#define NZt  2112   // 4*U + M

#define NUBLK 128   // u-blocks: 4 u-cols each (16 z-cols)
#define NEBLK 8     // e-blocks: 8 e-cols each
#define NBLK  136
#define NTHR  544   // 512 main threads + 1 gate warp
#define NTILES (33 * 512)

// ---------------- device scratch (free-running across graph replays) ----------------
__device__ float g_Z[(size_t)Tt * NZt * Bb];   // Z[t][n][b]
__device__ float g_hTT[2][Uu][Bb];             // hidden state TRANSPOSED [u][b], double buffered
__device__ float g_ze[Bb][Mm];                 // pre-softmax e logits

struct __align__(128) Cnt { unsigned int v; unsigned int pad[31]; };
__device__ Cnt g_hcnt8[8];    // striped h arrivals; stripe = bid>>4 = k-range (16/stripe/step)
__device__ Cnt g_ecnt;        // ze arrivals (8/step)
__device__ Cnt g_zdone;       // Z-phase barrier (+136 per replay)
__device__ Cnt g_tix;         // replay ticket counter (+136 per replay)

// SMEM float offsets
#define OFF_UD   0            // U duplicated [512 k][32] = 16384
#define OFF_CR   16384        // cring [64 slot][4 u][64 b] = 16384 (SMEM)
#define OFF_PS2  32768        // split-K partials [256 rows][68] = 17408
#define OFF_ZT   50176        // zt [16 c][65] = 1040
#define OFF_ZES  51216        // probs [64 b][65] = 4160
#define OFF_HST  55376        // h staging for out [4 uul][64 b] = 256
#define OFF_GF   55632        // flags: 1=ze ready t+1, 8..15=h stripe ready t
#define SMEM_F   55648        // 222592 bytes
// Z-phase scratch (overlaps UD/CR head, used strictly before recurrence)
#define OFF_XS0  0
#define OFF_WS0  4160
#define OFF_XS1  8256
#define OFF_WS1  12416

// ---------------- PTX helpers ----------------
__device__ __forceinline__ unsigned ld_acq(const unsigned int* p) {
    unsigned v;
    asm volatile("ld.acquire.gpu.global.u32 %0, [%1];" : "=r"(v) : "l"(p));
    return v;
}
__device__ __forceinline__ void red_rel(unsigned int* p) {
    asm volatile("red.release.gpu.global.add.u32 [%0], 1;" :: "l"(p));
}
__device__ __forceinline__ unsigned ld_acq_sh(const unsigned int* p) {
    unsigned v, a = (unsigned)__cvta_generic_to_shared(p);
    asm volatile("ld.acquire.cta.shared.u32 %0, [%1];" : "=r"(v) : "r"(a));
    return v;
}
__device__ __forceinline__ void st_rel_sh(unsigned int* p, unsigned v) {
    unsigned a = (unsigned)__cvta_generic_to_shared(p);
    asm volatile("st.release.cta.shared.u32 [%0], %1;" :: "r"(a), "r"(v));
}
#define MEMBAR_GL() asm volatile("membar.gl;" ::: "memory")
#define NBAR() asm volatile("bar.sync 1, 512;" ::: "memory")
#define TBAR(id) asm volatile("bar.sync %0, 256;" :: "r"(id) : "memory")

// packed fp32x2 FMA (FFMA2)
__device__ __forceinline__ unsigned long long pack2(float a, float b) {
    unsigned long long r;
    asm("mov.b64 %0, {%1, %2};" : "=l"(r) : "f"(a), "f"(b));
    return r;
}
__device__ __forceinline__ void fma2(unsigned long long& d,
                                     unsigned long long a, unsigned long long b) {
    asm("fma.rn.f32x2 %0, %1, %2, %0;" : "+l"(d) : "l"(a), "l"(b));
}
__device__ __forceinline__ void unpack2(unsigned long long v, float& a, float& b) {
    asm("mov.b64 {%0, %1}, %2;" : "=f"(a), "=f"(b) : "l"(v));
}
// 16B L2-only load (bypasses L1: h is cross-SM mutable)
__device__ __forceinline__ ulonglong2 ldcg2(const void* p) {
    ulonglong2 r;
    asm volatile("ld.global.cg.v2.u64 {%0, %1}, [%2];"
                 : "=l"(r.x), "=l"(r.y) : "l"(p));
    return r;
}

// ================= single fused kernel =================
__global__ __launch_bounds__(NTHR, 1) void xlstm_kernel(
    float* __restrict__ out, const float* __restrict__ x,
    const float* __restrict__ Wi, const float* __restrict__ Wf,
    const float* __restrict__ Wo, const float* __restrict__ Wc,
    const float* __restrict__ We,
    const float* __restrict__ bi, const float* __restrict__ bf,
    const float* __restrict__ bo, const float* __restrict__ bc,
    const float* __restrict__ be,
    const float* __restrict__ Ui, const float* __restrict__ Uf,
    const float* __restrict__ Uo, const float* __restrict__ Uc,
    const float* __restrict__ Ue)
{
    extern __shared__ float sm[];
    float* Ud  = sm + OFF_UD;
    float* cr  = sm + OFF_CR;
    float* ps2 = sm + OFF_PS2;
    float* zt  = sm + OFF_ZT;
    float* zes = sm + OFF_ZES;
    float* hst = sm + OFF_HST;
    unsigned int* gf = (unsigned int*)(sm + OFF_GF);
    __shared__ unsigned sR;

    const int bid = blockIdx.x;
    const int tid = threadIdx.x;
    const bool isE = (bid >= NUBLK);

    if (tid == 0) {
        unsigned old = atomicAdd(&g_tix.v, 1u);
        sR = old / (unsigned)NBLK;
    }
    if (tid < 16) gf[tid] = 0u;
    __syncthreads();
    const unsigned R = sR;
    const unsigned HB8 = R * 8192u;       // per-stripe base (16*512)
    const unsigned EB  = R * 4096u;       // e counter base (8*512)

    // ======== gate warp: lanes 0-7 publish per-stripe flags (no vote) ========
    if (tid >= 512) {
        const int lane = tid - 512;
        if (lane < 8) {
            for (int s2 = 1; s2 < Tt; s2++) {
                const unsigned tgt = HB8 + 16u * (unsigned)s2;
                while (ld_acq(&g_hcnt8[lane].v) < tgt) { }
                st_rel_sh(&gf[8 + lane], (unsigned)s2);
            }
        } else if (lane == 8 && !isE) {
            for (int t = 0; t < Tt; t++) {
                while (ld_acq(&g_ecnt.v) < EB + 8u * (unsigned)(t + 1)) { }
                st_rel_sh(&gf[1], (unsigned)(t + 1));
            }
        }
        return;
    }

    // ================= PHASE A: precompute Z =================
    {
        const int team = tid >> 8;
        const int ttid = tid & 255;
        float* xs = sm + (team ? OFF_XS1 : OFF_XS0);
        float* Ws = sm + (team ? OFF_WS1 : OFF_WS0);
        const int barid = 2 + team;
        const int ptx = ttid & 15, pty = ttid >> 4;

        for (int tile = bid * 2 + team; tile < NTILES; tile += NBLK * 2) {
            const int t  = tile / 33;
            const int nt = tile % 33;
            const float* W; const float* bv;
            switch (nt >> 3) {
                case 0:  W = Wi; bv = bi; break;
                case 1:  W = Wf; bv = bf; break;
                case 2:  W = Wo; bv = bo; break;
                case 3:  W = Wc; bv = bc; break;
                default: W = We; bv = be; break;
            }
            const int stride = (nt < 32) ? Uu : Mm;
            const int col0   = (nt & 7) * 64;

            unsigned long long acc01[4], acc23[4];
            {
                unsigned long long p01 = pack2(bv[col0 + ptx * 4 + 0], bv[col0 + ptx * 4 + 1]);
                unsigned long long p23 = pack2(bv[col0 + ptx * 4 + 2], bv[col0 + ptx * 4 + 3]);
                #pragma unroll
                for (int i = 0; i < 4; i++) { acc01[i] = p01; acc23[i] = p23; }
            }
            for (int kb = 0; kb < 4; kb++) {
                TBAR(barid);
                #pragma unroll
                for (int l = 0; l < 16; l++) {
                    int idx = l * 256 + ttid;
                    int b = idx >> 6, kk = idx & 63;
                    xs[b * 65 + kk] = x[(size_t)b * Tt * Dd + (size_t)t * Dd + kb * 64 + kk];
                }
                #pragma unroll
                for (int l = 0; l < 16; l++) {
                    int idx = l * 256 + ttid;
                    int kk = idx >> 6, nn = idx & 63;
                    Ws[kk * 64 + nn] = W[(size_t)(kb * 64 + kk) * stride + col0 + nn];
                }
                TBAR(barid);
                #pragma unroll 16
                for (int kk = 0; kk < 64; kk++) {
                    ulonglong2 wv = *reinterpret_cast<const ulonglong2*>(&Ws[kk * 64 + ptx * 4]);
                    #pragma unroll
                    for (int i = 0; i < 4; i++) {
                        float xv = xs[(pty * 4 + i) * 65 + kk];
                        unsigned long long xx = pack2(xv, xv);
                        fma2(acc01[i], xx, wv.x);
                        fma2(acc23[i], xx, wv.y);
                    }
                }
            }
            float a[4][4];
            #pragma unroll
            for (int i = 0; i < 4; i++) {
                unpack2(acc01[i], a[i][0], a[i][1]);
                unpack2(acc23[i], a[i][2], a[i][3]);
            }
            #pragma unroll
            for (int j = 0; j < 4; j++) {
                int n = nt * 64 + ptx * 4 + j;
                float4 v = make_float4(a[0][j], a[1][j], a[2][j], a[3][j]);
                *reinterpret_cast<float4*>(&g_Z[((size_t)t * NZt + n) * Bb + pty * 4]) = v;
            }
        }
    }
    NBAR();
    if (tid == 0) {
        MEMBAR_GL();
        red_rel(&g_zdone.v);
        while (ld_acq(&g_zdone.v) < (R + 1u) * (unsigned)NBLK) { }
    }
    NBAR();

    // ================= load duplicated U slice (once) =================
    const int u0 = bid * 4;
    const int m0 = (bid - NUBLK) * 8;
    {
        const int c = tid & 15, kk0 = tid >> 4;
        if (!isE) {
            const float* Ug;
            switch (c >> 2) {
                case 0:  Ug = Ui; break;
                case 1:  Ug = Uf; break;
                case 2:  Ug = Uo; break;
                default: Ug = Uc; break;
            }
            const int lc = u0 + (c & 3);
            for (int k = kk0; k < Uu; k += 32) {
                float v = Ug[(size_t)k * Uu + lc];
                Ud[k * 32 + c * 2] = v;
                Ud[k * 32 + c * 2 + 1] = v;
            }
        } else {
            for (int k = kk0; k < Uu; k += 32) {
                float v = (c < 8) ? Ue[(size_t)k * Mm + m0 + c] : 0.f;
                Ud[k * 32 + c * 2] = v;
                Ud[k * 32 + c * 2 + 1] = v;
            }
        }
    }
    NBAR();

    // ================= PHASE B: recurrence =================
    const int s    = tid >> 5;                    // warp = split-K slice (k in [32s,32s+32))
    const int lidw = tid & 31;
    const int bgrp = lidw & 7, cgrp = lidw >> 3;
    const int kbase = s * 32;
    const int rc = tid >> 5, rb = tid & 31;
    const int mystripe = 8 + (s >> 1);            // stripe flag this warp gates on

    int zcol; bool zvalid;
    if (!isE) { zcol = (rc >> 2) * Uu + u0 + (rc & 3); zvalid = true; }
    else      { zvalid = (rc < 8); zcol = 4 * Uu + m0 + (zvalid ? rc : 0); }

    for (int t = 0; t < Tt; t++) {
        float z0 = 0.f, z1 = 0.f;
        if (zvalid) {
            const float* zp = &g_Z[((size_t)t * NZt + zcol) * Bb];
            z0 = __ldcs(zp + rb);
            z1 = __ldcs(zp + 32 + rb);
        }

        if (t > 0) {
            // ---- per-warp stripe gate: start GEMM as soon as OUR k-range is ready ----
            while (ld_acq_sh(&gf[mystripe]) < (unsigned)t) { }

            // ---- GEMM: h direct from L2 (__ldcg), single pass over 64 b ----
            unsigned long long acc[2][2][4];
            #pragma unroll
            for (int a = 0; a < 2; a++)
                #pragma unroll
                for (int b2 = 0; b2 < 2; b2++)
                    #pragma unroll
                    for (int j = 0; j < 4; j++) acc[a][b2][j] = 0ull;

            const char* hbase = (const char*)(&g_hTT[t & 1][0][0] + kbase * 64 + bgrp * 4);
            const float* up = &Ud[kbase * 32 + cgrp * 8];
            #pragma unroll 8
            for (int k = 0; k < 32; k++) {
                ulonglong2 h0 = ldcg2(hbase + k * 256);          // b quad, half 0
                ulonglong2 h1 = ldcg2(hbase + k * 256 + 128);    // b quad, half 1
                ulonglong2 u01 = *reinterpret_cast<const ulonglong2*>(up + k * 32);
                ulonglong2 u23 = *reinterpret_cast<const ulonglong2*>(up + k * 32 + 4);
                fma2(acc[0][0][0], h0.x, u01.x);
                fma2(acc[0][0][1], h0.x, u01.y);
                fma2(acc[0][0][2], h0.x, u23.x);
                fma2(acc[0][0][3], h0.x, u23.y);
                fma2(acc[0][1][0], h0.y, u01.x);
                fma2(acc[0][1][1], h0.y, u01.y);
                fma2(acc[0][1][2], h0.y, u23.x);
                fma2(acc[0][1][3], h0.y, u23.y);
                fma2(acc[1][0][0], h1.x, u01.x);
                fma2(acc[1][0][1], h1.x, u01.y);
                fma2(acc[1][0][2], h1.x, u23.x);
                fma2(acc[1][0][3], h1.x, u23.y);
                fma2(acc[1][1][0], h1.y, u01.x);
                fma2(acc[1][1][1], h1.y, u01.y);
                fma2(acc[1][1][2], h1.y, u23.x);
                fma2(acc[1][1][3], h1.y, u23.y);
            }

            // ---- stage split-K partials (warp-private rows) ----
            #pragma unroll
            for (int hh = 0; hh < 2; hh++)
                #pragma unroll
                for (int j = 0; j < 4; j++) {
                    const int base = (s * 16 + cgrp * 4 + j) * 68 + hh * 32 + bgrp * 4;
                    *reinterpret_cast<unsigned long long*>(&ps2[base])     = acc[hh][0][j];
                    *reinterpret_cast<unsigned long long*>(&ps2[base + 2]) = acc[hh][1][j];
                }
            NBAR();

            // ---- reduce 16 slices + Z ----
            {
                float v0 = 0.f, v1 = 0.f;
                #pragma unroll
                for (int s2 = 0; s2 < 16; s2++) {
                    v0 += ps2[(s2 * 16 + rc) * 68 + rb];
                    v1 += ps2[(s2 * 16 + rc) * 68 + 32 + rb];
                }
                if (!isE) {
                    zt[rc * 65 + rb]      = v0 + z0;
                    zt[rc * 65 + 32 + rb] = v1 + z1;
                } else if (zvalid) {
                    g_ze[rb][m0 + rc]      = v0 + z0;
                    g_ze[32 + rb][m0 + rc] = v1 + z1;
                }
            }
            NBAR();
        } else {
            if (!isE) {
                zt[rc * 65 + rb]      = z0;
                zt[rc * 65 + 32 + rb] = z1;
            } else if (zvalid) {
                g_ze[rb][m0 + rc]      = z0;
                g_ze[32 + rb][m0 + rc] = z1;
            }
            NBAR();
        }

        if (isE) {
            if (tid == 0) { MEMBAR_GL(); red_rel(&g_ecnt.v); }
            continue;
        }

        // ---- u-blocks: activations early (registers), overlap the e wait ----
        float iv = 0.f, fv = 0.f, ov = 0.f, cv = 0.f;
        if (tid < 256) {
            const int uul = tid >> 6, b = tid & 63;
            float zi = zt[(uul)      * 65 + b];
            float zf = zt[(4 + uul)  * 65 + b];
            float zo = zt[(8 + uul)  * 65 + b];
            float zc = zt[(12 + uul) * 65 + b];
            iv = __fdividef(1.f, 1.f + __expf(-zi));
            fv = __fdividef(1.f, 1.f + __expf(-zf));
            ov = __fdividef(1.f, 1.f + __expf(-zo));
            float t2 = __expf(2.f * zc);
            cv = __fdividef(t2 - 1.f, t2 + 1.f);
        }
        // ---- e gate: all threads spin on SMEM flag ----
        while (ld_acq_sh(&gf[1]) < (unsigned)(t + 1)) { }

        // ---- local softmax: 8 lanes per batch row, direct from L2 ----
        {
            const int sb = tid >> 3, sq = tid & 7;
            const float4* zrow = reinterpret_cast<const float4*>(&g_ze[sb][sq * 8]);
            float4 v0 = __ldcg(zrow);
            float4 v1 = __ldcg(zrow + 1);
            float v[8] = {v0.x, v0.y, v0.z, v0.w, v1.x, v1.y, v1.z, v1.w};
            float mx = -1e30f;
            #pragma unroll
            for (int i = 0; i < 8; i++) mx = fmaxf(mx, v[i]);
            mx = fmaxf(mx, __shfl_xor_sync(0xffffffffu, mx, 1));
            mx = fmaxf(mx, __shfl_xor_sync(0xffffffffu, mx, 2));
            mx = fmaxf(mx, __shfl_xor_sync(0xffffffffu, mx, 4));
            float sum = 0.f;
            #pragma unroll
            for (int i = 0; i < 8; i++) { v[i] = __expf(v[i] - mx); sum += v[i]; }
            sum += __shfl_xor_sync(0xffffffffu, sum, 1);
            sum += __shfl_xor_sync(0xffffffffu, sum, 2);
            sum += __shfl_xor_sync(0xffffffffu, sum, 4);
            float inv = __fdividef(1.f, sum);
            #pragma unroll
            for (int i = 0; i < 8; i++) zes[sb * 65 + sq * 8 + i] = v[i] * inv;
        }
        NBAR();

        // ---- phase 2: ring read + update; h written straight to g_hTT ----
        if (tid < 256) {
            const int uul = tid >> 6, b = tid & 63;
            float p = 0.f;
            const float* zr = &zes[b * 65];
            if (t >= 64) {
                #pragma unroll
                for (int m = 0; m < 64; m++)
                    p += zr[m] * cr[(((t - 1 - m) & 63) * 4 + uul) * 64 + b];
            } else {
                for (int m = 0; m < t; m++)
                    p += zr[m] * cr[(((t - 1 - m) & 63) * 4 + uul) * 64 + b];
            }
            float c = fv * p + iv * cv;
            float t2c = __expf(2.f * c);
            float th = __fdividef(t2c - 1.f, t2c + 1.f);
            float h = ov * th;
            cr[((t & 63) * 4 + uul) * 64 + b] = c;
            g_hTT[(t + 1) & 1][u0 + uul][b] = h;     // coalesced across b
            hst[uul * 64 + b] = h;                   // staging for out only
        }
        NBAR();
        // arrival (covers g_hTT stores) in parallel with out stores
        if (tid == 0) { MEMBAR_GL(); red_rel(&g_hcnt8[bid >> 4].v); }
        else if (tid >= 64 && tid < 128) {
            const int b = tid - 64;
            float4 hv = make_float4(hst[b], hst[64 + b], hst[128 + b], hst[192 + b]);
            *reinterpret_cast<float4*>(&out[((size_t)b * Tt + t) * Uu + u0]) = hv;
        } else if (tid < 64 && tid > 0) {
            const int b = tid;
            float4 hv = make_float4(hst[b], hst[64 + b], hst[128 + b], hst[192 + b]);
            *reinterpret_cast<float4*>(&out[((size_t)b * Tt + t) * Uu + u0]) = hv;
        }
        if (tid == 0) {
            float4 hv = make_float4(hst[0], hst[64], hst[128], hst[192]);
            *reinterpret_cast<float4*>(&out[((size_t)0 * Tt + t) * Uu + u0]) = hv;
        }
        // no final barrier: hst WAR protected by next step's ps2 NBAR
    }
}

// ---------------- launch: ONE kernel ----------------
extern "C" void kernel_launch(void* const* d_in, const int* in_sizes, int n_in,
                              void* d_out, int out_size) {
    (void)in_sizes; (void)n_in; (void)out_size;
    const float* x  = (const float*)d_in[0];
    const float* Wi = (const float*)d_in[1];
    const float* Ui = (const float*)d_in[2];
    const float* bi = (const float*)d_in[3];
    const float* Wf = (const float*)d_in[4];
    const float* Uf = (const float*)d_in[5];
    const float* bf = (const float*)d_in[6];
    const float* Wo = (const float*)d_in[7];
    const float* Uo = (const float*)d_in[8];
    const float* bo = (const float*)d_in[9];
    const float* Wc = (const float*)d_in[10];
    const float* Uc = (const float*)d_in[11];
    const float* bc = (const float*)d_in[12];
    const float* We = (const float*)d_in[13];
    const float* Ue = (const float*)d_in[14];
    const float* be = (const float*)d_in[15];
    float* out = (float*)d_out;

    const size_t SMEM = (size_t)SMEM_F * sizeof(float);   // 222592 B
    cudaFuncSetAttribute(xlstm_kernel, cudaFuncAttributeMaxDynamicSharedMemorySize, (int)SMEM);

    xlstm_kernel<<<NBLK, NTHR, SMEM>>>(out, x,
        Wi, Wf, Wo, Wc, We, bi, bf, bo, bc, be,
        Ui, Uf, Uo, Uc, Ue);
}